// round 4
// baseline (speedup 1.0000x reference)
#include <cuda_runtime.h>
#include <cstdint>

// Problem constants
#define BN_TOK   32768          // B*N tokens
#define DDIM     1408
#define PDIM     256
#define K0       64
#define K1       128
#define K2       256
#define KTOT     448
#define KPAD     512
#define OUT_IDX  46137344       // BN_TOK * DDIM
#define OUT_LOSS 46235648       // OUT_IDX + 3*BN_TOK

// ---------------- device scratch ----------------
__device__ float g_zproj [BN_TOK * PDIM];       // 33.5 MB
__device__ float g_R     [BN_TOK * PDIM];       // 33.5 MB residual
__device__ float g_scores[BN_TOK * 256];        // 33.5 MB (ldc = 256)
__device__ float g_qcomb [BN_TOK * PDIM];       // 33.5 MB
__device__ float g_nr    [BN_TOK];              // ||r||^2 per token (current level)
__device__ float g_dmin  [BN_TOK];              // accumulated per-token loss
__device__ float g_EallT [PDIM * KPAD];         // [P, 512] transposed codebooks
__device__ float g_enorm [KPAD];
__device__ int   g_idx   [3 * BN_TOK];

// ---------------- SGEMM: C[M x N] = A[M x K] @ B[K x N] + bias ----------------
// BM=BN=128, BK=8, TM=TN=8, 256 threads. M%128==0, N%128==0, K%8==0.
__global__ __launch_bounds__(256, 2)
void sgemm_nn(int M, int N, int K, int lda, int ldb, int ldc,
              const float* __restrict__ A, const float* __restrict__ B,
              const float* __restrict__ bias, float* __restrict__ C) {
    __shared__ float As[8][128];
    __shared__ float Bs[8][128];
    const int tid  = threadIdx.x;
    const int cRow = blockIdx.y;
    const int cCol = blockIdx.x;
    const int tCol = tid & 15;
    const int tRow = tid >> 4;
    const int aRow = tid >> 1;
    const int aCol = (tid & 1) * 4;
    const int bRow = tid >> 5;
    const int bCol = (tid & 31) * 4;

    const float* Ab = A + (size_t)cRow * 128 * lda;
    const float* Bb = B + (size_t)cCol * 128;

    float acc[8][8];
    #pragma unroll
    for (int i = 0; i < 8; i++)
        #pragma unroll
        for (int j = 0; j < 8; j++) acc[i][j] = 0.f;

    for (int k0 = 0; k0 < K; k0 += 8) {
        float4 av = *(const float4*)(Ab + (size_t)aRow * lda + k0 + aCol);
        As[aCol + 0][aRow] = av.x;
        As[aCol + 1][aRow] = av.y;
        As[aCol + 2][aRow] = av.z;
        As[aCol + 3][aRow] = av.w;
        float4 bv = *(const float4*)(Bb + (size_t)(k0 + bRow) * ldb + bCol);
        *(float4*)&Bs[bRow][bCol] = bv;
        __syncthreads();
        #pragma unroll
        for (int k = 0; k < 8; k++) {
            float ar[8], br[8];
            #pragma unroll
            for (int i = 0; i < 8; i++) ar[i] = As[k][tRow * 8 + i];
            #pragma unroll
            for (int j = 0; j < 8; j++) br[j] = Bs[k][tCol * 8 + j];
            #pragma unroll
            for (int i = 0; i < 8; i++)
                #pragma unroll
                for (int j = 0; j < 8; j++)
                    acc[i][j] = fmaf(ar[i], br[j], acc[i][j]);
        }
        __syncthreads();
    }

    #pragma unroll
    for (int i = 0; i < 8; i++) {
        const int row = cRow * 128 + tRow * 8 + i;
        #pragma unroll
        for (int j = 0; j < 8; j += 4) {
            const int col = cCol * 128 + tCol * 8 + j;
            float4 v;
            v.x = acc[i][j + 0]; v.y = acc[i][j + 1];
            v.z = acc[i][j + 2]; v.w = acc[i][j + 3];
            if (bias) {
                v.x += bias[col + 0]; v.y += bias[col + 1];
                v.z += bias[col + 2]; v.w += bias[col + 3];
            }
            *(float4*)(C + (size_t)row * ldc + col) = v;
        }
    }
}

// ---------------- build E_all^T [P, 512] (cols >= 448 zero) ----------------
__global__ void prep_kernel(const float* __restrict__ e0,
                            const float* __restrict__ e1,
                            const float* __restrict__ e2) {
    int idx = blockIdx.x * blockDim.x + threadIdx.x;
    int p = idx / KPAD, j = idx % KPAD;
    float v = 0.f;
    if (j < K0)            v = e0[j * PDIM + p];
    else if (j < K0 + K1)  v = e1[(j - K0) * PDIM + p];
    else if (j < KTOT)     v = e2[(j - K0 - K1) * PDIM + p];
    g_EallT[p * KPAD + j] = v;
}

__device__ __forceinline__ float dot256(const float* __restrict__ a,
                                        const float* __restrict__ b) {
    const float4* a4 = (const float4*)a;
    const float4* b4 = (const float4*)b;
    float s = 0.f;
    #pragma unroll 8
    for (int i = 0; i < 64; i++) {
        float4 x = a4[i], y = b4[i];
        s = fmaf(x.x, y.x, s); s = fmaf(x.y, y.y, s);
        s = fmaf(x.z, y.z, s); s = fmaf(x.w, y.w, s);
    }
    return s;
}

// ---------------- codebook squared norms ----------------
__global__ void norm_kernel(const float* __restrict__ e0,
                            const float* __restrict__ e1,
                            const float* __restrict__ e2) {
    int j = blockIdx.x * blockDim.x + threadIdx.x;
    if (j >= KTOT) return;
    const float* r;
    if (j < K0)           r = e0 + j * PDIM;
    else if (j < K0 + K1) r = e1 + (j - K0) * PDIM;
    else                  r = e2 + (j - K0 - K1) * PDIM;
    g_enorm[j] = dot256(r, r);
}

// ---------------- per-token ||z_proj||^2 ----------------
__global__ void rownorm_kernel() {
    int t = blockIdx.x * 8 + (threadIdx.x >> 5);
    int lane = threadIdx.x & 31;
    const float4* row = (const float4*)(g_zproj + (size_t)t * PDIM);
    float s = 0.f;
    #pragma unroll
    for (int i = lane; i < 64; i += 32) {
        float4 v = row[i];
        s = fmaf(v.x, v.x, s); s = fmaf(v.y, v.y, s);
        s = fmaf(v.z, v.z, s); s = fmaf(v.w, v.w, s);
    }
    #pragma unroll
    for (int o = 16; o; o >>= 1) s += __shfl_down_sync(0xffffffffu, s, o);
    if (lane == 0) g_nr[t] = s;
}

// ---------------- per-level argmin (warp per token) ----------------
// dist = (nr - 2*s) + en, non-fused, mirroring the reference expression tree.
__device__ __forceinline__ void warp_argmin(float& bv, int& bi) {
    #pragma unroll
    for (int o = 16; o; o >>= 1) {
        float ov = __shfl_xor_sync(0xffffffffu, bv, o);
        int   oi = __shfl_xor_sync(0xffffffffu, bi, o);
        if (ov < bv || (ov == bv && oi < bi)) { bv = ov; bi = oi; }
    }
}

__global__ void argmin_kernel(int Kl, int enOff, int level, float* __restrict__ out) {
    const int warp = threadIdx.x >> 5, lane = threadIdx.x & 31;
    const int t = blockIdx.x * 8 + warp;
    const float* __restrict__ S = g_scores + (size_t)t * 256;
    const float nr = g_nr[t];

    float bv = 3.4e38f; int bi = 0;
    for (int j = lane; j < Kl; j += 32) {
        float s = S[j];
        float d = __fadd_rn(__fsub_rn(nr, __fmul_rn(2.f, s)), g_enorm[enOff + j]);
        if (d < bv) { bv = d; bi = j; }
    }
    warp_argmin(bv, bi);
    if (lane == 0) {
        g_idx[level * BN_TOK + t] = bi;
        out[OUT_IDX + level * BN_TOK + t] = (float)bi;
    }
}

// ---------------- residual update: Rout = Rin - emb[idx]; nr, loss ----------
template<bool STORE_LOSS>
__global__ void update_kernel(const float* __restrict__ Rin,
                              float* __restrict__ Rout,
                              const float* __restrict__ emb,
                              const int* __restrict__ idx) {
    const int t = blockIdx.x;
    const int p = threadIdx.x;            // 64 threads, float4 each
    const int code = idx[t];
    const float4* rin = (const float4*)(Rin + (size_t)t * PDIM);
    const float4* er  = (const float4*)(emb + (size_t)code * PDIM);
    float4* rout = (float4*)(Rout + (size_t)t * PDIM);

    float4 r = rin[p], e = er[p];
    float4 d;
    d.x = r.x - e.x; d.y = r.y - e.y; d.z = r.z - e.z; d.w = r.w - e.w;
    rout[p] = d;
    float s = d.x * d.x + d.y * d.y + d.z * d.z + d.w * d.w;

    const int lane = p & 31, w = p >> 5;
    #pragma unroll
    for (int o = 16; o; o >>= 1) s += __shfl_down_sync(0xffffffffu, s, o);
    __shared__ float red[2];
    if (lane == 0) red[w] = s;
    __syncthreads();
    if (p == 0) {
        float tot = red[0] + red[1];
        g_nr[t] = tot;                     // ||r_next||^2 for next level's dist
        if (STORE_LOSS) g_dmin[t] = tot;   // == sum((z_q - r)^2) for this level
        else            g_dmin[t] += tot;
    }
}

// ---------------- gather q0+q1+q2; finalize loss ----------------
__global__ void gather_kernel(const float* __restrict__ e0,
                              const float* __restrict__ e1,
                              const float* __restrict__ e2,
                              float* __restrict__ out) {
    const int t = blockIdx.x, p = threadIdx.x;
    const int i0 = g_idx[t], i1 = g_idx[BN_TOK + t], i2 = g_idx[2 * BN_TOK + t];
    g_qcomb[(size_t)t * PDIM + p] =
        e0[i0 * PDIM + p] + e1[i1 * PDIM + p] + e2[i2 * PDIM + p];

    if (blockIdx.x == 0) {
        __shared__ float red[256];
        float s = 0.f;
        for (int i = p; i < BN_TOK; i += 256) s += g_dmin[i];
        red[p] = s;
        __syncthreads();
        for (int st = 128; st; st >>= 1) {
            if (p < st) red[p] += red[p + st];
            __syncthreads();
        }
        if (p == 0)
            out[OUT_LOSS] = 0.25f * red[0] / ((float)BN_TOK * (float)PDIM * 3.f);
    }
}

// ---------------- launcher ----------------
extern "C" void kernel_launch(void* const* d_in, const int* in_sizes, int n_in,
                              void* d_out, int out_size) {
    const float* z     = (const float*)d_in[0];
    const float* W_in  = (const float*)d_in[1];
    const float* b_in  = (const float*)d_in[2];
    const float* W_out = (const float*)d_in[3];
    const float* b_out = (const float*)d_in[4];
    const float* e0    = (const float*)d_in[5];
    const float* e1    = (const float*)d_in[6];
    const float* e2    = (const float*)d_in[7];
    float* out = (float*)d_out;

    float *zproj, *R, *scores, *eallt, *qcomb;
    int   *idx;
    cudaGetSymbolAddress((void**)&zproj,  g_zproj);
    cudaGetSymbolAddress((void**)&R,      g_R);
    cudaGetSymbolAddress((void**)&scores, g_scores);
    cudaGetSymbolAddress((void**)&eallt,  g_EallT);
    cudaGetSymbolAddress((void**)&qcomb,  g_qcomb);
    cudaGetSymbolAddress((void**)&idx,    g_idx);

    // codebook prep (independent of z path)
    prep_kernel<<<(PDIM * KPAD) / 256, 256>>>(e0, e1, e2);
    norm_kernel<<<(KTOT + 255) / 256, 256>>>(e0, e1, e2);

    // z_proj = z @ W_in + b_in        [32768,1408] x [1408,256]
    sgemm_nn<<<dim3(PDIM / 128, BN_TOK / 128), 256>>>(
        BN_TOK, PDIM, DDIM, DDIM, PDIM, PDIM, z, W_in, b_in, zproj);
    rownorm_kernel<<<BN_TOK / 8, 256>>>();

    // ---- level 0 (K=64; compute 128 padded cols of E_all^T) ----
    sgemm_nn<<<dim3(1, BN_TOK / 128), 256>>>(
        BN_TOK, 128, PDIM, PDIM, KPAD, 256, zproj, eallt + 0, nullptr, scores);
    argmin_kernel<<<BN_TOK / 8, 256>>>(K0, 0, 0, out);
    update_kernel<true><<<BN_TOK, 64>>>(zproj, R, e0, idx);

    // ---- level 1 (K=128) ----
    sgemm_nn<<<dim3(1, BN_TOK / 128), 256>>>(
        BN_TOK, 128, PDIM, PDIM, KPAD, 256, R, eallt + K0, nullptr, scores);
    argmin_kernel<<<BN_TOK / 8, 256>>>(K1, K0, 1, out);
    update_kernel<false><<<BN_TOK, 64>>>(R, R, e1, idx + BN_TOK);

    // ---- level 2 (K=256) ----
    sgemm_nn<<<dim3(2, BN_TOK / 128), 256>>>(
        BN_TOK, 256, PDIM, PDIM, KPAD, 256, R, eallt + K0 + K1, nullptr, scores);
    argmin_kernel<<<BN_TOK / 8, 256>>>(K2, K0 + K1, 2, out);
    update_kernel<false><<<BN_TOK, 64>>>(R, R, e2, idx + 2 * BN_TOK);

    // q_comb = e0[i0] + e1[i1] + e2[i2]; finalize loss
    gather_kernel<<<BN_TOK, 256>>>(e0, e1, e2, out);

    // z_q_out = q_comb @ W_out + b_out   [32768,256] x [256,1408]
    sgemm_nn<<<dim3(DDIM / 128, BN_TOK / 128), 256>>>(
        BN_TOK, DDIM, PDIM, PDIM, DDIM, DDIM, qcomb, W_out, b_out, out);
}

// round 7
// speedup vs baseline: 1.1335x; 1.1335x over previous
#include <cuda_runtime.h>
#include <cstdint>

// ---------------- problem constants ----------------
#define BN_TOK 32768
#define DDIM   1408
#define PDIM   256
#define KC0    64
#define KC1    128
#define KC2    256
#define OUT_IDX  46137344
#define OUT_LOSS 46235648

// ---------------- device scratch ----------------
__device__ float g_zproj[BN_TOK * PDIM];
__device__ float g_R    [BN_TOK * PDIM];
__device__ float g_qcomb[BN_TOK * PDIM];
__device__ float g_WinT [PDIM * DDIM];     // [256][1408]  (W_in^T)
__device__ float g_WoutT[DDIM * PDIM];     // [1408][256]  (W_out^T)
__device__ float g_nr   [BN_TOK];
__device__ float g_dmin [BN_TOK];
__device__ float g_enorm[512];
__device__ int   g_cand [8 * BN_TOK];      // cand j of block bx: [(bx*4+j)*BN_TOK + t]

// ---------------- helpers ----------------
__device__ __forceinline__ float tf32_rna(float x) {
    uint32_t u; asm("cvt.rna.tf32.f32 %0, %1;" : "=r"(u) : "f"(x));
    return __uint_as_float(u);
}
__device__ __forceinline__ void mma_tf32(float* c, const uint32_t* a, const uint32_t* b) {
    asm volatile("mma.sync.aligned.m16n8k8.row.col.f32.tf32.tf32.f32 "
        "{%0,%1,%2,%3}, {%4,%5,%6,%7}, {%8,%9}, {%0,%1,%2,%3};"
        : "+f"(c[0]), "+f"(c[1]), "+f"(c[2]), "+f"(c[3])
        : "r"(a[0]), "r"(a[1]), "r"(a[2]), "r"(a[3]), "r"(b[0]), "r"(b[1]));
}
// k-dependent XOR swizzle: conflict-free fragment LDS, cheap STS
__device__ __forceinline__ int swz(int k, int c) {
    return c ^ ((k & 3) << 3) ^ (((k >> 2) & 1) << 2);
}
// insert (dv, cg) into sorted top-4 list (ascending d, index tie-break)
__device__ __forceinline__ void ins4(float* d, int* ci, float dv, int cg) {
    #pragma unroll
    for (int q = 0; q < 4; q++) {
        bool better = dv < d[q] || (dv == d[q] && cg < ci[q]);
        float td = d[q]; int ti = ci[q];
        if (better) { d[q] = dv; ci[q] = cg; dv = td; cg = ti; }
    }
}

// =====================================================================
// tf32 3-product warp-MMA GEMM.  C[128 x NT per block] = A @ B^T
// A: [M][K] row-major.  B: [N][K] row-major (K-major operand).
// MODE 0: C = acc + bias.   MODE 1: fused top-4 candidate extraction.
// 256 threads = 8 warps (4 m x 2 n).  BK = 16, double-buffered.
// =====================================================================
template<int NT, int MODE>
__global__ void __launch_bounds__(256, 2)
mma_gemm(int K, int lda, int ldb, int ldc,
         const float* __restrict__ A, const float* __restrict__ B,
         const float* __restrict__ bias, float* __restrict__ C,
         const float* __restrict__ nrp, const float* __restrict__ enp,
         int* __restrict__ candp) {
    constexpr int WARP_N = NT / 2;
    constexpr int NTL    = WARP_N / 8;           // n-tiles per warp
    constexpr int STG    = 16 * 128 * 2 + 16 * NT * 2;   // floats / buffer
    extern __shared__ float sm[];
    const int tid = threadIdx.x;
    const int w = tid >> 5, lane = tid & 31;
    const int wm = w & 3, wn = w >> 2;
    const int g = lane >> 2, t = lane & 3;
    const int by = blockIdx.y, bx = blockIdx.x;

    const float* Ab = A + (size_t)by * 128 * lda;
    const float* Bb = B + (size_t)bx * NT * ldb;

    float acc[2][NTL][4];
    #pragma unroll
    for (int mi = 0; mi < 2; mi++)
        #pragma unroll
        for (int ni = 0; ni < NTL; ni++)
            #pragma unroll
            for (int q = 0; q < 4; q++) acc[mi][ni][q] = 0.f;

    float4 ra[2], rb[NT / 64];
    auto gload = [&](int st) {
        const int k0 = st * 16;
        #pragma unroll
        for (int i = 0; i < 2; i++) {
            int fid = tid + i * 256, m = fid >> 2, kq = (fid & 3) * 4;
            ra[i] = *(const float4*)(Ab + (size_t)m * lda + k0 + kq);
        }
        #pragma unroll
        for (int i = 0; i < NT / 64; i++) {
            int fid = tid + i * 256, n = fid >> 2, kq = (fid & 3) * 4;
            rb[i] = *(const float4*)(Bb + (size_t)n * ldb + k0 + kq);
        }
    };
    auto sstore = [&](int buf) {
        float* AsH = sm + buf * STG;
        float* AsL = AsH + 2048;
        float* BsH = AsL + 2048;
        float* BsL = BsH + 16 * NT;
        #pragma unroll
        for (int i = 0; i < 2; i++) {
            int fid = tid + i * 256, m = fid >> 2, rot = fid & 3, kq = rot * 4;
            float v[4] = { ra[i].x, ra[i].y, ra[i].z, ra[i].w };
            #pragma unroll
            for (int c = 0; c < 4; c++) {
                int cc = (c + rot) & 3, k = kq + cc;
                float hi = tf32_rna(v[cc]);
                float lo = tf32_rna(v[cc] - hi);
                int idx = k * 128 + swz(k, m);
                AsH[idx] = hi; AsL[idx] = lo;
            }
        }
        #pragma unroll
        for (int i = 0; i < NT / 64; i++) {
            int fid = tid + i * 256, n = fid >> 2, rot = fid & 3, kq = rot * 4;
            float v[4] = { rb[i].x, rb[i].y, rb[i].z, rb[i].w };
            #pragma unroll
            for (int c = 0; c < 4; c++) {
                int cc = (c + rot) & 3, k = kq + cc;
                float hi = tf32_rna(v[cc]);
                float lo = tf32_rna(v[cc] - hi);
                int idx = k * NT + swz(k, n);
                BsH[idx] = hi; BsL[idx] = lo;
            }
        }
    };
    auto compute = [&](int buf) {
        const float* AsH = sm + buf * STG;
        const float* AsL = AsH + 2048;
        const float* BsH = AsL + 2048;
        const float* BsL = BsH + 16 * NT;
        #pragma unroll
        for (int s = 0; s < 2; s++) {
            const int kl = 8 * s + t, kh = kl + 4;
            uint32_t ah[2][4], al[2][4];
            #pragma unroll
            for (int mi = 0; mi < 2; mi++) {
                int m0 = wm * 32 + mi * 16 + g;
                int i0 = kl * 128 + swz(kl, m0);
                int i1 = kl * 128 + swz(kl, m0 + 8);
                int i2 = kh * 128 + swz(kh, m0);
                int i3 = kh * 128 + swz(kh, m0 + 8);
                ah[mi][0] = __float_as_uint(AsH[i0]); ah[mi][1] = __float_as_uint(AsH[i1]);
                ah[mi][2] = __float_as_uint(AsH[i2]); ah[mi][3] = __float_as_uint(AsH[i3]);
                al[mi][0] = __float_as_uint(AsL[i0]); al[mi][1] = __float_as_uint(AsL[i1]);
                al[mi][2] = __float_as_uint(AsL[i2]); al[mi][3] = __float_as_uint(AsL[i3]);
            }
            #pragma unroll
            for (int ni = 0; ni < NTL; ni++) {
                int n0 = wn * WARP_N + ni * 8 + g;
                int j0 = kl * NT + swz(kl, n0);
                int j1 = kh * NT + swz(kh, n0);
                uint32_t bh[2] = { __float_as_uint(BsH[j0]), __float_as_uint(BsH[j1]) };
                uint32_t bl[2] = { __float_as_uint(BsL[j0]), __float_as_uint(BsL[j1]) };
                #pragma unroll
                for (int mi = 0; mi < 2; mi++) {
                    mma_tf32(acc[mi][ni], ah[mi], bh);
                    mma_tf32(acc[mi][ni], al[mi], bh);
                    mma_tf32(acc[mi][ni], ah[mi], bl);
                }
            }
        }
    };

    const int S = K / 16;
    gload(0);
    sstore(0);
    __syncthreads();
    for (int st = 0; st < S; st++) {
        if (st + 1 < S) gload(st + 1);
        compute(st & 1);
        __syncthreads();
        if (st + 1 < S) { sstore((st + 1) & 1); __syncthreads(); }
    }

    // ---------------- epilogue ----------------
    if (MODE == 0) {
        #pragma unroll
        for (int mi = 0; mi < 2; mi++)
            #pragma unroll
            for (int ni = 0; ni < NTL; ni++) {
                int row = by * 128 + wm * 32 + mi * 16 + g;
                int col = bx * NT + wn * WARP_N + ni * 8 + 2 * t;
                float b0 = bias[col], b1 = bias[col + 1];
                float2 v0 = make_float2(acc[mi][ni][0] + b0, acc[mi][ni][1] + b1);
                float2 v1 = make_float2(acc[mi][ni][2] + b0, acc[mi][ni][3] + b1);
                *(float2*)(C + (size_t)row * ldc + col)       = v0;
                *(float2*)(C + (size_t)(row + 8) * ldc + col) = v1;
            }
    } else {
        __syncthreads();                         // smem reuse
        float* sd = sm;                          // [2][128][4] floats
        int*   si = (int*)(sm + 1024);           // [2][128][4] ints
        #pragma unroll
        for (int mi = 0; mi < 2; mi++)
            #pragma unroll
            for (int h = 0; h < 2; h++) {
                const int rloc = wm * 32 + mi * 16 + h * 8 + g;
                const float nr = nrp[by * 128 + rloc];
                float d[4] = { 3.4e38f, 3.4e38f, 3.4e38f, 3.4e38f };
                int   ci[4] = { 0, 0, 0, 0 };
                #pragma unroll
                for (int ni = 0; ni < NTL; ni++)
                    #pragma unroll
                    for (int cc = 0; cc < 2; cc++) {
                        int cg = bx * NT + wn * WARP_N + ni * 8 + 2 * t + cc;
                        float s = acc[mi][ni][h * 2 + cc];
                        float dd = (nr - 2.f * s) + enp[cg];
                        ins4(d, ci, dd, cg);
                    }
                #pragma unroll
                for (int o = 1; o < 4; o <<= 1) {
                    float od[4]; int oi[4];
                    #pragma unroll
                    for (int q = 0; q < 4; q++) {
                        od[q] = __shfl_xor_sync(0xffffffffu, d[q], o);
                        oi[q] = __shfl_xor_sync(0xffffffffu, ci[q], o);
                    }
                    #pragma unroll
                    for (int q = 0; q < 4; q++) ins4(d, ci, od[q], oi[q]);
                }
                if (t == 0) {
                    int base = (wn * 128 + rloc) * 4;
                    #pragma unroll
                    for (int q = 0; q < 4; q++) { sd[base + q] = d[q]; si[base + q] = ci[q]; }
                }
            }
        __syncthreads();
        if (tid < 128) {
            float d[4]; int ci[4];
            #pragma unroll
            for (int q = 0; q < 4; q++) { d[q] = sd[tid * 4 + q]; ci[q] = si[tid * 4 + q]; }
            #pragma unroll
            for (int q = 0; q < 4; q++)
                ins4(d, ci, sd[(128 + tid) * 4 + q], si[(128 + tid) * 4 + q]);
            size_t tok = (size_t)by * 128 + tid;
            #pragma unroll
            for (int q = 0; q < 4; q++)
                candp[(size_t)(bx * 4 + q) * BN_TOK + tok] = ci[q];
        }
    }
}

// ---------------- 32x32 tiled transpose: out[C][R] = in[R][C] ----------------
__global__ void transpose_kernel(const float* __restrict__ in, float* __restrict__ out,
                                 int R, int Cc) {
    __shared__ float tile[32][33];
    int bxp = blockIdx.x * 32, byp = blockIdx.y * 32;
    int tx = threadIdx.x, ty = threadIdx.y;
    #pragma unroll
    for (int i = 0; i < 4; i++)
        tile[ty + i * 8][tx] = in[(size_t)(byp + ty + i * 8) * Cc + bxp + tx];
    __syncthreads();
    #pragma unroll
    for (int i = 0; i < 4; i++)
        out[(size_t)(bxp + ty + i * 8) * R + byp + tx] = tile[tx][ty + i * 8];
}

// ---------------- codebook squared norms ----------------
__device__ __forceinline__ float dot256d(const float* a, const float* b) {
    const float4* a4 = (const float4*)a; const float4* b4 = (const float4*)b;
    float s = 0.f;
    #pragma unroll 8
    for (int i = 0; i < 64; i++) {
        float4 x = a4[i], y = b4[i];
        s = fmaf(x.x, y.x, s); s = fmaf(x.y, y.y, s);
        s = fmaf(x.z, y.z, s); s = fmaf(x.w, y.w, s);
    }
    return s;
}
__global__ void norm_kernel(const float* __restrict__ e0, const float* __restrict__ e1,
                            const float* __restrict__ e2) {
    int j = blockIdx.x * blockDim.x + threadIdx.x;
    if (j >= 448) return;
    const float* r;
    if (j < KC0)            r = e0 + j * PDIM;
    else if (j < KC0 + KC1) r = e1 + (j - KC0) * PDIM;
    else                    r = e2 + (j - KC0 - KC1) * PDIM;
    g_enorm[j] = dot256d(r, r);
}

// ---------------- per-token ||z_proj||^2 ----------------
__global__ void rownorm_kernel() {
    int tk = blockIdx.x * 8 + (threadIdx.x >> 5);
    int lane = threadIdx.x & 31;
    const float4* row = (const float4*)(g_zproj + (size_t)tk * PDIM);
    float s = 0.f;
    #pragma unroll
    for (int i = lane; i < 64; i += 32) {
        float4 v = row[i];
        s = fmaf(v.x, v.x, s); s = fmaf(v.y, v.y, s);
        s = fmaf(v.z, v.z, s); s = fmaf(v.w, v.w, s);
    }
    #pragma unroll
    for (int o = 16; o; o >>= 1) s += __shfl_down_sync(0xffffffffu, s, o);
    if (lane == 0) g_nr[tk] = s;
}

// ---------------- refine: exact fp32 re-rank of candidates + residual update
// MODE 0: Rout = g_R, loss init.  1: in-place.  2: qcomb = zproj - r_new.
template<int NC, int MODE>
__global__ void refine_kernel(const float* __restrict__ Rin, float* __restrict__ Rout,
                              const float* __restrict__ emb, int enoff, int level,
                              const int* __restrict__ candp, float* __restrict__ out) {
    const int warp = threadIdx.x >> 5, lane = threadIdx.x & 31;
    const int tk = blockIdx.x * 8 + warp;
    const float4* r4 = (const float4*)(Rin + (size_t)tk * PDIM);
    float4 ra = r4[lane * 2], rb = r4[lane * 2 + 1];
    float bestd = 3.4e38f; int bestc = 0x7fffffff;
    #pragma unroll
    for (int j = 0; j < NC; j++) {
        const int cj = candp[(size_t)j * BN_TOK + tk];
        const float4* e4 = (const float4*)(emb + (size_t)cj * PDIM);
        float4 ea = e4[lane * 2], eb = e4[lane * 2 + 1];
        float s = 0.f;
        s = fmaf(ra.x, ea.x, s); s = fmaf(ra.y, ea.y, s);
        s = fmaf(ra.z, ea.z, s); s = fmaf(ra.w, ea.w, s);
        s = fmaf(rb.x, eb.x, s); s = fmaf(rb.y, eb.y, s);
        s = fmaf(rb.z, eb.z, s); s = fmaf(rb.w, eb.w, s);
        #pragma unroll
        for (int o = 16; o; o >>= 1) s += __shfl_xor_sync(0xffffffffu, s, o);
        // rr constant per token: ranking by en - 2s is equivalent; keep exact form
        float d = __fadd_rn(g_enorm[enoff + cj], __fmul_rn(-2.f, s));
        if (d < bestd || (d == bestd && cj < bestc)) { bestd = d; bestc = cj; }
    }
    const float4* e4 = (const float4*)(emb + (size_t)bestc * PDIM);
    float4 ea = e4[lane * 2], eb = e4[lane * 2 + 1];
    float4 na, nb;
    na.x = ra.x - ea.x; na.y = ra.y - ea.y; na.z = ra.z - ea.z; na.w = ra.w - ea.w;
    nb.x = rb.x - eb.x; nb.y = rb.y - eb.y; nb.z = rb.z - eb.z; nb.w = rb.w - eb.w;
    float ns = 0.f;
    ns = fmaf(na.x, na.x, ns); ns = fmaf(na.y, na.y, ns);
    ns = fmaf(na.z, na.z, ns); ns = fmaf(na.w, na.w, ns);
    ns = fmaf(nb.x, nb.x, ns); ns = fmaf(nb.y, nb.y, ns);
    ns = fmaf(nb.z, nb.z, ns); ns = fmaf(nb.w, nb.w, ns);
    #pragma unroll
    for (int o = 16; o; o >>= 1) ns += __shfl_xor_sync(0xffffffffu, ns, o);

    if (MODE != 2) {
        float4* ro = (float4*)(Rout + (size_t)tk * PDIM);
        ro[lane * 2] = na; ro[lane * 2 + 1] = nb;
    } else {
        const float4* z4 = (const float4*)(g_zproj + (size_t)tk * PDIM);
        float4 za = z4[lane * 2], zb = z4[lane * 2 + 1];
        float4 qa, qb;
        qa.x = za.x - na.x; qa.y = za.y - na.y; qa.z = za.z - na.z; qa.w = za.w - na.w;
        qb.x = zb.x - nb.x; qb.y = zb.y - nb.y; qb.z = zb.z - nb.z; qb.w = zb.w - nb.w;
        float4* qo = (float4*)(g_qcomb + (size_t)tk * PDIM);
        qo[lane * 2] = qa; qo[lane * 2 + 1] = qb;
    }
    if (lane == 0) {
        g_nr[tk] = ns;
        if (MODE == 0) g_dmin[tk] = ns; else g_dmin[tk] += ns;
        out[OUT_IDX + level * BN_TOK + tk] = (float)bestc;
    }
}

// ---------------- loss finalize ----------------
__global__ void loss_final(float* __restrict__ out) {
    __shared__ float red[256];
    const int p = threadIdx.x;
    float s = 0.f;
    for (int i = p; i < BN_TOK; i += 256) s += g_dmin[i];
    red[p] = s;
    __syncthreads();
    for (int st = 128; st; st >>= 1) {
        if (p < st) red[p] += red[p + st];
        __syncthreads();
    }
    if (p == 0)
        out[OUT_LOSS] = 0.25f * red[0] / ((float)BN_TOK * (float)PDIM * 3.f);
}

// ---------------- launcher ----------------
extern "C" void kernel_launch(void* const* d_in, const int* in_sizes, int n_in,
                              void* d_out, int out_size) {
    const float* z     = (const float*)d_in[0];
    const float* W_in  = (const float*)d_in[1];
    const float* b_in  = (const float*)d_in[2];
    const float* W_out = (const float*)d_in[3];
    const float* b_out = (const float*)d_in[4];
    const float* e0    = (const float*)d_in[5];
    const float* e1    = (const float*)d_in[6];
    const float* e2    = (const float*)d_in[7];
    float* out = (float*)d_out;

    float *zproj, *R, *qcomb, *winT, *woutT, *nr, *enorm;
    int *cand;
    cudaGetSymbolAddress((void**)&zproj, g_zproj);
    cudaGetSymbolAddress((void**)&R,     g_R);
    cudaGetSymbolAddress((void**)&qcomb, g_qcomb);
    cudaGetSymbolAddress((void**)&winT,  g_WinT);
    cudaGetSymbolAddress((void**)&woutT, g_WoutT);
    cudaGetSymbolAddress((void**)&nr,    g_nr);
    cudaGetSymbolAddress((void**)&enorm, g_enorm);
    cudaGetSymbolAddress((void**)&cand,  g_cand);

    const int SM128 = 2 * (16 * 128 * 2 + 16 * 128 * 2) * 4;   // 65536
    const int SM64  = 2 * (16 * 128 * 2 + 16 * 64  * 2) * 4;   // 49152
    cudaFuncSetAttribute(mma_gemm<128, 0>, cudaFuncAttributeMaxDynamicSharedMemorySize, SM128);
    cudaFuncSetAttribute(mma_gemm<128, 1>, cudaFuncAttributeMaxDynamicSharedMemorySize, SM128);
    cudaFuncSetAttribute(mma_gemm<64, 1>,  cudaFuncAttributeMaxDynamicSharedMemorySize, SM64);

    // prep
    transpose_kernel<<<dim3(PDIM / 32, DDIM / 32), dim3(32, 8)>>>(W_in, winT, DDIM, PDIM);
    transpose_kernel<<<dim3(DDIM / 32, PDIM / 32), dim3(32, 8)>>>(W_out, woutT, PDIM, DDIM);
    norm_kernel<<<2, 256>>>(e0, e1, e2);

    // z_proj = z @ W_in + b_in     [32768,1408] x [1408,256]
    mma_gemm<128, 0><<<dim3(2, BN_TOK / 128), 256, SM128>>>(
        DDIM, DDIM, DDIM, PDIM, z, winT, b_in, zproj, nullptr, nullptr, nullptr);
    rownorm_kernel<<<BN_TOK / 8, 256>>>();

    // level 0 (K_codes = 64) -> 4 candidates
    mma_gemm<64, 1><<<dim3(1, BN_TOK / 128), 256, SM64>>>(
        PDIM, PDIM, PDIM, 0, zproj, e0, nullptr, nullptr, nr, enorm, cand);
    refine_kernel<4, 0><<<BN_TOK / 8, 256>>>(zproj, R, e0, 0, 0, cand, out);

    // level 1 (K_codes = 128) -> 4 candidates
    mma_gemm<128, 1><<<dim3(1, BN_TOK / 128), 256, SM128>>>(
        PDIM, PDIM, PDIM, 0, R, e1, nullptr, nullptr, nr, enorm + KC0, cand);
    refine_kernel<4, 1><<<BN_TOK / 8, 256>>>(R, R, e1, KC0, 1, cand, out);

    // level 2 (K_codes = 256; two N-blocks -> 8 candidates)
    mma_gemm<128, 1><<<dim3(2, BN_TOK / 128), 256, SM128>>>(
        PDIM, PDIM, PDIM, 0, R, e2, nullptr, nullptr, nr, enorm + KC0 + KC1, cand);
    refine_kernel<8, 2><<<BN_TOK / 8, 256>>>(R, nullptr, e2, KC0 + KC1, 2, cand, out);

    loss_final<<<1, 256>>>(out);

    // z_q_out = qcomb @ W_out + b_out   [32768,256] x [256,1408]
    mma_gemm<128, 0><<<dim3(DDIM / 128, BN_TOK / 128), 256, SM128>>>(
        PDIM, PDIM, PDIM, DDIM, qcomb, woutT, b_out, out, nullptr, nullptr, nullptr);
}

// round 8
// speedup vs baseline: 1.1976x; 1.0565x over previous
#include <cuda_runtime.h>
#include <cstdint>

// ---------------- problem constants ----------------
#define BN_TOK 32768
#define DDIM   1408
#define PDIM   256
#define KC0    64
#define KC1    128
#define KC2    256
#define OUT_IDX  46137344
#define OUT_LOSS 46235648

// ---------------- device scratch ----------------
__device__ float g_zproj[BN_TOK * PDIM];
__device__ float g_R    [BN_TOK * PDIM];
__device__ float g_qcomb[BN_TOK * PDIM];
__device__ float g_nr   [BN_TOK];
__device__ float g_dmin [BN_TOK];
__device__ float g_enorm[512];
__device__ int   g_cand [8 * BN_TOK];
// pre-split (hi/lo tf32) pre-swizzled B operand images
__device__ float g_BWin [720896];   // N=256,  K=1408, NT=128
__device__ float g_BWout[720896];   // N=1408, K=256,  NT=128
__device__ float g_Be0  [32768];    // N=64,   K=256,  NT=64
__device__ float g_Be1  [65536];    // N=128,  K=256,  NT=128
__device__ float g_Be2  [131072];   // N=256,  K=256,  NT=128

// ---------------- helpers ----------------
__device__ __forceinline__ float tf32_rna(float x) {
    uint32_t u; asm("cvt.rna.tf32.f32 %0, %1;" : "=r"(u) : "f"(x));
    return __uint_as_float(u);
}
__device__ __forceinline__ void mma_tf32(float* c, const uint32_t* a, const uint32_t* b) {
    asm volatile("mma.sync.aligned.m16n8k8.row.col.f32.tf32.tf32.f32 "
        "{%0,%1,%2,%3}, {%4,%5,%6,%7}, {%8,%9}, {%0,%1,%2,%3};"
        : "+f"(c[0]), "+f"(c[1]), "+f"(c[2]), "+f"(c[3])
        : "r"(a[0]), "r"(a[1]), "r"(a[2]), "r"(a[3]), "r"(b[0]), "r"(b[1]));
}
__device__ __forceinline__ uint32_t smem_u32(const void* p) {
    uint32_t a;
    asm("{ .reg .u64 t; cvta.to.shared.u64 t, %1; cvt.u32.u64 %0, t; }" : "=r"(a) : "l"(p));
    return a;
}
__device__ __forceinline__ void cp16(uint32_t dst, const void* src) {
    asm volatile("cp.async.ca.shared.global [%0], [%1], 16;" :: "r"(dst), "l"(src));
}
#define CP_COMMIT() asm volatile("cp.async.commit_group;" ::: "memory")
#define CP_WAIT1()  asm volatile("cp.async.wait_group 1;" ::: "memory")

// insert (dv, cg) into sorted top-4 list (ascending d, index tie-break)
__device__ __forceinline__ void ins4(float* d, int* ci, float dv, int cg) {
    #pragma unroll
    for (int q = 0; q < 4; q++) {
        bool better = dv < d[q] || (dv == d[q] && cg < ci[q]);
        float td = d[q]; int ti = ci[q];
        if (better) { d[q] = dv; ci[q] = cg; dv = td; cg = ti; }
    }
}

// ---------------- B image prep: split fp32 -> (hi,lo) tf32, fragment order --
// image word layout per (nb, kb): ((wn*NI+ni)*2+s)*64 + (g*4+t)*2 + w ; hi then lo
template<int NT>
__global__ void bprep(const float* __restrict__ src, float* __restrict__ img,
                      int K, int ld, int trans, int total) {
    int i = blockIdx.x * 256 + threadIdx.x;
    if (i >= total) return;
    constexpr int NI = NT / 16;
    int word = i & (NT * 16 - 1);
    int rest = i / (NT * 16);
    int kb = rest % (K / 16);
    int nb = rest / (K / 16);
    int w = word & 1;
    int t = (word >> 1) & 3;
    int g = (word >> 3) & 7;
    int s = (word >> 6) & 1;
    int wnni = word >> 7;
    int wn = wnni / NI, ni = wnni % NI;
    int n = nb * NT + wn * (NT / 2) + ni * 8 + g;
    int k = kb * 16 + s * 8 + t + w * 4;
    float x = trans ? src[(size_t)k * ld + n] : src[(size_t)n * ld + k];
    float hi = tf32_rna(x), lo = tf32_rna(x - hi);
    size_t base = (size_t)rest * (NT * 32);
    img[base + word] = hi;
    img[base + NT * 16 + word] = lo;
}

// =====================================================================
// tf32 3-product warp-MMA GEMM.  CTA tile 256m x NT.  8 warps (4m x 2n),
// warp tile 64 x (NT/2).  BK=16.  A double-buffered (in-kernel split into
// fragment-ordered smem), B triple-buffered cp.async from pre-split image.
// MODE 0: C = acc + bias.  MODE 1: fused top-4 candidate extraction.
// =====================================================================
template<int NT, int MODE>
__global__ void __launch_bounds__(256, 1)
mma_gemm(int K, int lda, int ldc,
         const float* __restrict__ A, const float* __restrict__ Bimg,
         const float* __restrict__ bias, float* __restrict__ C,
         const float* __restrict__ nrp, const float* __restrict__ enp,
         int* __restrict__ candp) {
    constexpr int NI = NT / 16;              // 8-wide n tiles per warp
    constexpr int NB = NT * 32;              // B floats per stage (hi+lo)
    extern __shared__ float sm[];
    const int tid = threadIdx.x;
    const int w = tid >> 5, lane = tid & 31;
    const int wm = w & 3, wn = w >> 2;
    const int g = lane >> 2, t = lane & 3;
    const int bx = blockIdx.x, by = blockIdx.y;
    const int KB = K / 16;

    const float* Ab = A + (size_t)by * 256 * lda;
    const uint32_t smBu = smem_u32(sm + 16384);

    float acc[4][NI][4];
    #pragma unroll
    for (int mi = 0; mi < 4; mi++)
        #pragma unroll
        for (int ni = 0; ni < NI; ni++)
            #pragma unroll
            for (int q = 0; q < 4; q++) acc[mi][ni][q] = 0.f;

    float4 ra[4];
    auto gloadA = [&](int st) {
        const int k0 = st * 16;
        #pragma unroll
        for (int i = 0; i < 4; i++) {
            int fid = tid + i * 256;
            int m = fid >> 2, rot = fid & 3;
            ra[i] = *(const float4*)(Ab + (size_t)m * lda + k0 + rot * 4);
        }
    };
    auto sstoreA = [&](int abuf) {
        float* dH = sm + abuf * 8192;
        float* dL = dH + 4096;
        #pragma unroll
        for (int i = 0; i < 4; i++) {
            int fid = tid + i * 256;
            int m = fid >> 2, rot = fid & 3;
            float v[4] = { ra[i].x, ra[i].y, ra[i].z, ra[i].w };
            int basem = ((m >> 4) << 8) + ((m & 7) << 4) + ((m >> 3) & 1);
            #pragma unroll
            for (int c = 0; c < 4; c++) {
                int cc = (c + rot) & 3;
                int k = rot * 4 + cc;
                float x = v[cc];
                float hi = tf32_rna(x);
                float lo = tf32_rna(x - hi);
                int idx = basem + ((k >> 3) << 7) + ((k & 3) << 2) + (((k >> 2) & 1) << 1);
                dH[idx] = hi; dL[idx] = lo;
            }
        }
    };
    auto cpB = [&](int st, int bbuf) {
        const float* src = Bimg + ((size_t)bx * KB + st) * NB + tid * (NT / 8);
        uint32_t dst = smBu + (bbuf * NB + tid * (NT / 8)) * 4;
        #pragma unroll
        for (int j = 0; j < NT / 32; j++) cp16(dst + j * 16, src + j * 4);
    };
    auto compute = [&](int abuf, int bbuf) {
        const float* AsH = sm + abuf * 8192;
        const float* AsL = AsH + 4096;
        const float* BsH = sm + 16384 + bbuf * NB;
        const float* BsL = BsH + NT * 16;
        #pragma unroll
        for (int s = 0; s < 2; s++) {
            float4 ah[4], al[4];
            #pragma unroll
            for (int mi = 0; mi < 4; mi++) {
                int q = (((wm * 4 + mi) * 2 + s) * 32 + lane) * 4;
                ah[mi] = *(const float4*)(AsH + q);
                al[mi] = *(const float4*)(AsL + q);
            }
            #pragma unroll
            for (int ni = 0; ni < NI; ni++) {
                int o = ((wn * NI + ni) * 2 + s) * 64 + lane * 2;
                float2 bh = *(const float2*)(BsH + o);
                float2 bl = *(const float2*)(BsL + o);
                uint32_t bhu[2] = { __float_as_uint(bh.x), __float_as_uint(bh.y) };
                uint32_t blu[2] = { __float_as_uint(bl.x), __float_as_uint(bl.y) };
                #pragma unroll
                for (int mi = 0; mi < 4; mi++) {
                    uint32_t ahu[4] = { __float_as_uint(ah[mi].x), __float_as_uint(ah[mi].y),
                                        __float_as_uint(ah[mi].z), __float_as_uint(ah[mi].w) };
                    uint32_t alu[4] = { __float_as_uint(al[mi].x), __float_as_uint(al[mi].y),
                                        __float_as_uint(al[mi].z), __float_as_uint(al[mi].w) };
                    mma_tf32(acc[mi][ni], ahu, bhu);
                    mma_tf32(acc[mi][ni], alu, bhu);
                    mma_tf32(acc[mi][ni], ahu, blu);
                }
            }
        }
    };

    // prologue
    cpB(0, 0); CP_COMMIT();
    if (KB > 1) cpB(1, 1);
    CP_COMMIT();
    gloadA(0);
    sstoreA(0);
    CP_WAIT1();
    __syncthreads();

    for (int st = 0; st < KB; st++) {
        if (st + 1 < KB) gloadA(st + 1);
        compute(st & 1, st % 3);
        if (st + 2 < KB) cpB(st + 2, (st + 2) % 3);
        CP_COMMIT();
        if (st + 1 < KB) sstoreA((st + 1) & 1);
        CP_WAIT1();
        __syncthreads();
    }

    // ---------------- epilogue ----------------
    if (MODE == 0) {
        #pragma unroll
        for (int mi = 0; mi < 4; mi++)
            #pragma unroll
            for (int ni = 0; ni < NI; ni++) {
                int row = by * 256 + wm * 64 + mi * 16 + g;
                int col = bx * NT + wn * (NT / 2) + ni * 8 + 2 * t;
                float b0 = bias[col], b1 = bias[col + 1];
                *(float2*)(C + (size_t)row * ldc + col) =
                    make_float2(acc[mi][ni][0] + b0, acc[mi][ni][1] + b1);
                *(float2*)(C + (size_t)(row + 8) * ldc + col) =
                    make_float2(acc[mi][ni][2] + b0, acc[mi][ni][3] + b1);
            }
    } else {
        __syncthreads();
        float* sd = sm;                       // [2][256][4]
        int*   si = (int*)(sm + 2048);
        #pragma unroll
        for (int mi = 0; mi < 4; mi++)
            #pragma unroll
            for (int h = 0; h < 2; h++) {
                int rloc = wm * 64 + mi * 16 + h * 8 + g;
                float nr = nrp[by * 256 + rloc];
                float d[4] = { 3.4e38f, 3.4e38f, 3.4e38f, 3.4e38f };
                int   ci[4] = { 0, 0, 0, 0 };
                #pragma unroll
                for (int ni = 0; ni < NI; ni++)
                    #pragma unroll
                    for (int cc = 0; cc < 2; cc++) {
                        int cg = bx * NT + wn * (NT / 2) + ni * 8 + 2 * t + cc;
                        float dd = (nr - 2.f * acc[mi][ni][h * 2 + cc]) + enp[cg];
                        ins4(d, ci, dd, cg);
                    }
                #pragma unroll
                for (int o = 1; o < 4; o <<= 1) {
                    float od[4]; int oi[4];
                    #pragma unroll
                    for (int q = 0; q < 4; q++) {
                        od[q] = __shfl_xor_sync(0xffffffffu, d[q], o);
                        oi[q] = __shfl_xor_sync(0xffffffffu, ci[q], o);
                    }
                    #pragma unroll
                    for (int q = 0; q < 4; q++) ins4(d, ci, od[q], oi[q]);
                }
                if (t == 0) {
                    int base = (wn * 256 + rloc) * 4;
                    #pragma unroll
                    for (int q = 0; q < 4; q++) { sd[base + q] = d[q]; si[base + q] = ci[q]; }
                }
            }
        __syncthreads();
        {
            float d[4]; int ci[4];
            #pragma unroll
            for (int q = 0; q < 4; q++) { d[q] = sd[tid * 4 + q]; ci[q] = si[tid * 4 + q]; }
            #pragma unroll
            for (int q = 0; q < 4; q++)
                ins4(d, ci, sd[(256 + tid) * 4 + q], si[(256 + tid) * 4 + q]);
            size_t tok = (size_t)by * 256 + tid;
            #pragma unroll
            for (int q = 0; q < 4; q++)
                candp[(size_t)(bx * 4 + q) * BN_TOK + tok] = ci[q];
        }
    }
}

// ---------------- codebook squared norms ----------------
__device__ __forceinline__ float dot256d(const float* a, const float* b) {
    const float4* a4 = (const float4*)a; const float4* b4 = (const float4*)b;
    float s = 0.f;
    #pragma unroll 8
    for (int i = 0; i < 64; i++) {
        float4 x = a4[i], y = b4[i];
        s = fmaf(x.x, y.x, s); s = fmaf(x.y, y.y, s);
        s = fmaf(x.z, y.z, s); s = fmaf(x.w, y.w, s);
    }
    return s;
}
__global__ void norm_kernel(const float* __restrict__ e0, const float* __restrict__ e1,
                            const float* __restrict__ e2) {
    int j = blockIdx.x * blockDim.x + threadIdx.x;
    if (j >= 448) return;
    const float* r;
    if (j < KC0)            r = e0 + j * PDIM;
    else if (j < KC0 + KC1) r = e1 + (j - KC0) * PDIM;
    else                    r = e2 + (j - KC0 - KC1) * PDIM;
    g_enorm[j] = dot256d(r, r);
}

// ---------------- per-token ||z_proj||^2 ----------------
__global__ void rownorm_kernel() {
    int tk = blockIdx.x * 8 + (threadIdx.x >> 5);
    int lane = threadIdx.x & 31;
    const float4* row = (const float4*)(g_zproj + (size_t)tk * PDIM);
    float s = 0.f;
    #pragma unroll
    for (int i = lane; i < 64; i += 32) {
        float4 v = row[i];
        s = fmaf(v.x, v.x, s); s = fmaf(v.y, v.y, s);
        s = fmaf(v.z, v.z, s); s = fmaf(v.w, v.w, s);
    }
    #pragma unroll
    for (int o = 16; o; o >>= 1) s += __shfl_down_sync(0xffffffffu, s, o);
    if (lane == 0) g_nr[tk] = s;
}

// ---------------- refine: exact fp32 re-rank of candidates + residual update
// MODE 0: Rout = g_R, loss init.  1: in-place.  2: qcomb = zproj - r_new.
template<int NC, int MODE>
__global__ void refine_kernel(const float* __restrict__ Rin, float* __restrict__ Rout,
                              const float* __restrict__ emb, int enoff, int level,
                              const int* __restrict__ candp, float* __restrict__ out) {
    const int warp = threadIdx.x >> 5, lane = threadIdx.x & 31;
    const int tk = blockIdx.x * 8 + warp;
    const float4* r4 = (const float4*)(Rin + (size_t)tk * PDIM);
    float4 ra = r4[lane * 2], rb = r4[lane * 2 + 1];
    float bestd = 3.4e38f; int bestc = 0x7fffffff;
    #pragma unroll
    for (int j = 0; j < NC; j++) {
        const int cj = candp[(size_t)j * BN_TOK + tk];
        const float4* e4 = (const float4*)(emb + (size_t)cj * PDIM);
        float4 ea = e4[lane * 2], eb = e4[lane * 2 + 1];
        float s = 0.f;
        s = fmaf(ra.x, ea.x, s); s = fmaf(ra.y, ea.y, s);
        s = fmaf(ra.z, ea.z, s); s = fmaf(ra.w, ea.w, s);
        s = fmaf(rb.x, eb.x, s); s = fmaf(rb.y, eb.y, s);
        s = fmaf(rb.z, eb.z, s); s = fmaf(rb.w, eb.w, s);
        #pragma unroll
        for (int o = 16; o; o >>= 1) s += __shfl_xor_sync(0xffffffffu, s, o);
        float d = __fadd_rn(g_enorm[enoff + cj], __fmul_rn(-2.f, s));
        if (d < bestd || (d == bestd && cj < bestc)) { bestd = d; bestc = cj; }
    }
    const float4* e4 = (const float4*)(emb + (size_t)bestc * PDIM);
    float4 ea = e4[lane * 2], eb = e4[lane * 2 + 1];
    float4 na, nb;
    na.x = ra.x - ea.x; na.y = ra.y - ea.y; na.z = ra.z - ea.z; na.w = ra.w - ea.w;
    nb.x = rb.x - eb.x; nb.y = rb.y - eb.y; nb.z = rb.z - eb.z; nb.w = rb.w - eb.w;
    float ns = 0.f;
    ns = fmaf(na.x, na.x, ns); ns = fmaf(na.y, na.y, ns);
    ns = fmaf(na.z, na.z, ns); ns = fmaf(na.w, na.w, ns);
    ns = fmaf(nb.x, nb.x, ns); ns = fmaf(nb.y, nb.y, ns);
    ns = fmaf(nb.z, nb.z, ns); ns = fmaf(nb.w, nb.w, ns);
    #pragma unroll
    for (int o = 16; o; o >>= 1) ns += __shfl_xor_sync(0xffffffffu, ns, o);

    if (MODE != 2) {
        float4* ro = (float4*)(Rout + (size_t)tk * PDIM);
        ro[lane * 2] = na; ro[lane * 2 + 1] = nb;
    } else {
        const float4* z4 = (const float4*)(g_zproj + (size_t)tk * PDIM);
        float4 za = z4[lane * 2], zb = z4[lane * 2 + 1];
        float4 qa, qb;
        qa.x = za.x - na.x; qa.y = za.y - na.y; qa.z = za.z - na.z; qa.w = za.w - na.w;
        qb.x = zb.x - nb.x; qb.y = zb.y - nb.y; qb.z = zb.z - nb.z; qb.w = zb.w - nb.w;
        float4* qo = (float4*)(g_qcomb + (size_t)tk * PDIM);
        qo[lane * 2] = qa; qo[lane * 2 + 1] = qb;
    }
    if (lane == 0) {
        g_nr[tk] = ns;
        if (MODE == 0) g_dmin[tk] = ns; else g_dmin[tk] += ns;
        out[OUT_IDX + level * BN_TOK + tk] = (float)bestc;
    }
}

// ---------------- loss finalize ----------------
__global__ void loss_final(float* __restrict__ out) {
    __shared__ float red[256];
    const int p = threadIdx.x;
    float s = 0.f;
    for (int i = p; i < BN_TOK; i += 256) s += g_dmin[i];
    red[p] = s;
    __syncthreads();
    for (int st = 128; st; st >>= 1) {
        if (p < st) red[p] += red[p + st];
        __syncthreads();
    }
    if (p == 0)
        out[OUT_LOSS] = 0.25f * red[0] / ((float)BN_TOK * (float)PDIM * 3.f);
}

// ---------------- launcher ----------------
extern "C" void kernel_launch(void* const* d_in, const int* in_sizes, int n_in,
                              void* d_out, int out_size) {
    const float* z     = (const float*)d_in[0];
    const float* W_in  = (const float*)d_in[1];
    const float* b_in  = (const float*)d_in[2];
    const float* W_out = (const float*)d_in[3];
    const float* b_out = (const float*)d_in[4];
    const float* e0    = (const float*)d_in[5];
    const float* e1    = (const float*)d_in[6];
    const float* e2    = (const float*)d_in[7];
    float* out = (float*)d_out;

    float *zproj, *R, *qcomb, *nr, *enorm;
    float *bwin, *bwout, *be0, *be1, *be2;
    int *cand;
    cudaGetSymbolAddress((void**)&zproj, g_zproj);
    cudaGetSymbolAddress((void**)&R,     g_R);
    cudaGetSymbolAddress((void**)&qcomb, g_qcomb);
    cudaGetSymbolAddress((void**)&nr,    g_nr);
    cudaGetSymbolAddress((void**)&enorm, g_enorm);
    cudaGetSymbolAddress((void**)&cand,  g_cand);
    cudaGetSymbolAddress((void**)&bwin,  g_BWin);
    cudaGetSymbolAddress((void**)&bwout, g_BWout);
    cudaGetSymbolAddress((void**)&be0,   g_Be0);
    cudaGetSymbolAddress((void**)&be1,   g_Be1);
    cudaGetSymbolAddress((void**)&be2,   g_Be2);

    const int SM128 = (16384 + 3 * 128 * 32) * 4;   // 114688
    const int SM64  = (16384 + 3 * 64 * 32) * 4;    //  90112
    cudaFuncSetAttribute(mma_gemm<128, 0>, cudaFuncAttributeMaxDynamicSharedMemorySize, SM128);
    cudaFuncSetAttribute(mma_gemm<128, 1>, cudaFuncAttributeMaxDynamicSharedMemorySize, SM128);
    cudaFuncSetAttribute(mma_gemm<64, 1>,  cudaFuncAttributeMaxDynamicSharedMemorySize, SM64);

    // operand prep (B images) + codebook norms
    bprep<128><<<(256 * 1408 + 255) / 256, 256>>>(W_in,  bwin,  1408, 256,  1, 256 * 1408);
    bprep<128><<<(1408 * 256 + 255) / 256, 256>>>(W_out, bwout, 256,  1408, 1, 1408 * 256);
    bprep<64> <<<(64 * 256 + 255) / 256,   256>>>(e0,    be0,   256,  256,  0, 64 * 256);
    bprep<128><<<(128 * 256 + 255) / 256,  256>>>(e1,    be1,   256,  256,  0, 128 * 256);
    bprep<128><<<(256 * 256 + 255) / 256,  256>>>(e2,    be2,   256,  256,  0, 256 * 256);
    norm_kernel<<<2, 256>>>(e0, e1, e2);

    // z_proj = z @ W_in + b_in     [32768,1408] x [1408,256]
    mma_gemm<128, 0><<<dim3(2, BN_TOK / 256), 256, SM128>>>(
        DDIM, DDIM, PDIM, z, bwin, b_in, zproj, nullptr, nullptr, nullptr);
    rownorm_kernel<<<BN_TOK / 8, 256>>>();

    // level 0 (64 codes) -> 4 candidates
    mma_gemm<64, 1><<<dim3(1, BN_TOK / 256), 256, SM64>>>(
        PDIM, PDIM, 0, zproj, be0, nullptr, nullptr, nr, enorm, cand);
    refine_kernel<4, 0><<<BN_TOK / 8, 256>>>(zproj, R, e0, 0, 0, cand, out);

    // level 1 (128 codes) -> 4 candidates
    mma_gemm<128, 1><<<dim3(1, BN_TOK / 256), 256, SM128>>>(
        PDIM, PDIM, 0, R, be1, nullptr, nullptr, nr, enorm + KC0, cand);
    refine_kernel<4, 1><<<BN_TOK / 8, 256>>>(R, R, e1, KC0, 1, cand, out);

    // level 2 (256 codes; two N-blocks) -> 8 candidates
    mma_gemm<128, 1><<<dim3(2, BN_TOK / 256), 256, SM128>>>(
        PDIM, PDIM, 0, R, be2, nullptr, nullptr, nr, enorm + KC0 + KC1, cand);
    refine_kernel<8, 2><<<BN_TOK / 8, 256>>>(R, nullptr, e2, KC0 + KC1, 2, cand, out);

    loss_final<<<1, 256>>>(out);

    // z_q_out = qcomb @ W_out + b_out   [32768,256] x [256,1408]
    mma_gemm<128, 0><<<dim3(11, BN_TOK / 256), 256, SM128>>>(
        PDIM, PDIM, DDIM, qcomb, bwout, b_out, out, nullptr, nullptr, nullptr);
}

// round 9
// speedup vs baseline: 1.3205x; 1.1026x over previous
#include <cuda_runtime.h>
#include <cstdint>

// ---------------- problem constants ----------------
#define BN_TOK 32768
#define DDIM   1408
#define PDIM   256
#define KC0    64
#define KC1    128
#define KC2    256
#define OUT_IDX  46137344
#define OUT_LOSS 46235648

// ---------------- device scratch ----------------
__device__ float g_zproj[BN_TOK * PDIM];
__device__ float g_R    [BN_TOK * PDIM];
__device__ float g_qcomb[BN_TOK * PDIM];
__device__ float g_nr   [BN_TOK];
__device__ float g_dmin [BN_TOK];
__device__ float g_enorm[512];
__device__ int   g_cand [8 * BN_TOK];
// pre-split (hi/lo tf32) fragment-ordered B operand images
__device__ float g_BWin [720896];   // N=256,  K=1408, NT=128
__device__ float g_BWout[720896];   // N=1408, K=256,  NT=128
__device__ float g_Be0  [32768];    // N=64,   K=256,  NT=64
__device__ float g_Be1  [65536];    // N=128,  K=256,  NT=128
__device__ float g_Be2  [131072];   // N=256,  K=256,  NT=128

// ---------------- helpers ----------------
__device__ __forceinline__ float tf32_rna(float x) {
    uint32_t u; asm("cvt.rna.tf32.f32 %0, %1;" : "=r"(u) : "f"(x));
    return __uint_as_float(u);
}
__device__ __forceinline__ void mma_tf32(float* c, const uint32_t* a, const uint32_t* b) {
    asm volatile("mma.sync.aligned.m16n8k8.row.col.f32.tf32.tf32.f32 "
        "{%0,%1,%2,%3}, {%4,%5,%6,%7}, {%8,%9}, {%0,%1,%2,%3};"
        : "+f"(c[0]), "+f"(c[1]), "+f"(c[2]), "+f"(c[3])
        : "r"(a[0]), "r"(a[1]), "r"(a[2]), "r"(a[3]), "r"(b[0]), "r"(b[1]));
}
__device__ __forceinline__ uint32_t smem_u32(const void* p) {
    uint32_t a;
    asm("{ .reg .u64 t; cvta.to.shared.u64 t, %1; cvt.u32.u64 %0, t; }" : "=r"(a) : "l"(p));
    return a;
}
__device__ __forceinline__ void cp16(uint32_t dst, const void* src) {
    asm volatile("cp.async.ca.shared.global [%0], [%1], 16;" :: "r"(dst), "l"(src));
}
#define CP_COMMIT() asm volatile("cp.async.commit_group;" ::: "memory")
#define CP_WAIT1()  asm volatile("cp.async.wait_group 1;" ::: "memory")

// insert (dv, cg) into sorted top-4 list (ascending d, index tie-break)
__device__ __forceinline__ void ins4(float* d, int* ci, float dv, int cg) {
    #pragma unroll
    for (int q = 0; q < 4; q++) {
        bool better = dv < d[q] || (dv == d[q] && cg < ci[q]);
        float td = d[q]; int ti = ci[q];
        if (better) { d[q] = dv; ci[q] = cg; dv = td; cg = ti; }
    }
}

// ---------------- B image prep (PROVEN round-8 layout) ----------------
// word per (nb,kb): ((wn*NI+ni)*2+s)*64 + (g*4+t)*2 + w ; hi block then lo block
template<int NT>
__global__ void bprep(const float* __restrict__ src, float* __restrict__ img,
                      int K, int ld, int trans, int total) {
    int i = blockIdx.x * 256 + threadIdx.x;
    if (i >= total) return;
    constexpr int NI = NT / 16;
    int word = i & (NT * 16 - 1);
    int rest = i / (NT * 16);
    int kb = rest % (K / 16);
    int nb = rest / (K / 16);
    int w = word & 1;
    int t = (word >> 1) & 3;
    int g = (word >> 3) & 7;
    int s = (word >> 6) & 1;
    int wnni = word >> 7;
    int wn = wnni / NI, ni = wnni % NI;
    int n = nb * NT + wn * (NT / 2) + ni * 8 + g;
    int k = kb * 16 + s * 8 + t + w * 4;
    float x = trans ? src[(size_t)k * ld + n] : src[(size_t)n * ld + k];
    float hi = tf32_rna(x), lo = tf32_rna(x - hi);
    size_t base = (size_t)rest * (NT * 32);
    img[base + word] = hi;
    img[base + NT * 16 + word] = lo;
}

// =====================================================================
// tf32 3-product warp-MMA GEMM.  CTA tile 128m x NT.  8 warps (4m x 2n),
// warp tile 32 x (NT/2).  BK=16.  A double-buffered, fragment-ordered smem
// with XOR-chunk layout; B triple-buffered cp.async from pre-split image.
// MODE 0: C = acc + bias.  MODE 1: fused top-4 candidate extraction.
// =====================================================================
template<int NT, int MODE>
__global__ void __launch_bounds__(256, 2)
mma_gemm(int K, int lda, int ldc,
         const float* __restrict__ A, const float* __restrict__ Bimg,
         const float* __restrict__ bias, float* __restrict__ C,
         const float* __restrict__ nrp, const float* __restrict__ enp,
         int* __restrict__ candp) {
    constexpr int NI   = NT / 16;            // 8-wide n tiles per warp
    constexpr int NB   = NT * 32;            // B floats per stage (hi+lo)
    constexpr int ABUF = 4096;               // A floats per buffer (hi+lo)
    extern __shared__ float sm[];
    const int tid = threadIdx.x;
    const int w = tid >> 5, lane = tid & 31;
    const int wm = w & 3, wn = w >> 2;
    const int g = lane >> 2, t = lane & 3;
    const int bx = blockIdx.x, by = blockIdx.y;
    const int KB = K / 16;
    const int chunkp_c = lane ^ ((lane >> 2) & 7);    // consumer chunk perm

    const float* Ab = A + (size_t)by * 128 * lda;
    const uint32_t smBu = smem_u32(sm + 2 * ABUF);

    // producer coords: thread owns rows (m, m+8), one k-quad (rot)
    const int pp = tid >> 2, prot = tid & 3;
    const int pwmi = pp >> 3, pg = pp & 7;
    const int pm = pwmi * 16 + pg;

    float acc[2][NI][4];
    #pragma unroll
    for (int mi = 0; mi < 2; mi++)
        #pragma unroll
        for (int ni = 0; ni < NI; ni++)
            #pragma unroll
            for (int q = 0; q < 4; q++) acc[mi][ni][q] = 0.f;

    float4 ra0, ra1;
    auto gloadA = [&](int st) {
        const int k0 = st * 16 + prot * 4;
        ra0 = *(const float4*)(Ab + (size_t)pm * lda + k0);
        ra1 = *(const float4*)(Ab + (size_t)(pm + 8) * lda + k0);
    };
    auto sstoreA = [&](int abuf) {
        float* AsH = sm + abuf * ABUF;
        float* AsL = AsH + 2048;
        float v0[4] = { ra0.x, ra0.y, ra0.z, ra0.w };
        float v1[4] = { ra1.x, ra1.y, ra1.z, ra1.w };
        #pragma unroll
        for (int c = 0; c < 4; c++) {
            int cc = (c + prot) & 3;
            int k  = prot * 4 + cc;
            int s  = k >> 3, u = (k >> 2) & 1, tt = k & 3;
            int chunk  = pg * 4 + tt;
            int chunkp = chunk ^ pg;                 // ((chunk>>2)&7) == pg
            int widx = ((pwmi * 2 + s) * 32 + chunkp) * 4 + 2 * u;
            float h0 = tf32_rna(v0[cc]), l0 = tf32_rna(v0[cc] - h0);
            float h1 = tf32_rna(v1[cc]), l1 = tf32_rna(v1[cc] - h1);
            *(float2*)(AsH + widx) = make_float2(h0, h1);
            *(float2*)(AsL + widx) = make_float2(l0, l1);
        }
    };
    auto cpB = [&](int st, int bbuf) {
        const float* src = Bimg + ((size_t)bx * KB + st) * NB + tid * (NB / 256);
        uint32_t dst = smBu + (bbuf * NB + tid * (NB / 256)) * 4;
        #pragma unroll
        for (int j = 0; j < NB / 1024; j++) cp16(dst + j * 16, src + j * 4);
    };
    auto compute = [&](int abuf, int bbuf) {
        const float* AsH = sm + abuf * ABUF;
        const float* AsL = AsH + 2048;
        const float* BsH = sm + 2 * ABUF + bbuf * NB;
        const float* BsL = BsH + NT * 16;
        #pragma unroll
        for (int s = 0; s < 2; s++) {
            float4 ah[2], al[2];
            #pragma unroll
            for (int mi = 0; mi < 2; mi++) {
                int q = (((wm * 2 + mi) * 2 + s) * 32 + chunkp_c) * 4;
                ah[mi] = *(const float4*)(AsH + q);
                al[mi] = *(const float4*)(AsL + q);
            }
            #pragma unroll
            for (int ni = 0; ni < NI; ni++) {
                int o = ((wn * NI + ni) * 2 + s) * 64 + lane * 2;
                float2 bh = *(const float2*)(BsH + o);
                float2 bl = *(const float2*)(BsL + o);
                uint32_t bhu[2] = { __float_as_uint(bh.x), __float_as_uint(bh.y) };
                uint32_t blu[2] = { __float_as_uint(bl.x), __float_as_uint(bl.y) };
                #pragma unroll
                for (int mi = 0; mi < 2; mi++) {
                    uint32_t ahu[4] = { __float_as_uint(ah[mi].x), __float_as_uint(ah[mi].y),
                                        __float_as_uint(ah[mi].z), __float_as_uint(ah[mi].w) };
                    uint32_t alu[4] = { __float_as_uint(al[mi].x), __float_as_uint(al[mi].y),
                                        __float_as_uint(al[mi].z), __float_as_uint(al[mi].w) };
                    mma_tf32(acc[mi][ni], ahu, bhu);
                    mma_tf32(acc[mi][ni], alu, bhu);
                    mma_tf32(acc[mi][ni], ahu, blu);
                }
            }
        }
    };

    // prologue
    cpB(0, 0); CP_COMMIT();
    if (KB > 1) cpB(1, 1);
    CP_COMMIT();
    gloadA(0);
    sstoreA(0);
    CP_WAIT1();
    __syncthreads();

    for (int st = 0; st < KB; st++) {
        if (st + 1 < KB) gloadA(st + 1);
        compute(st & 1, st % 3);
        if (st + 2 < KB) cpB(st + 2, (st + 2) % 3);
        CP_COMMIT();
        if (st + 1 < KB) sstoreA((st + 1) & 1);
        CP_WAIT1();
        __syncthreads();
    }

    // ---------------- epilogue ----------------
    if (MODE == 0) {
        #pragma unroll
        for (int mi = 0; mi < 2; mi++)
            #pragma unroll
            for (int ni = 0; ni < NI; ni++) {
                int row = by * 128 + wm * 32 + mi * 16 + g;
                int col = bx * NT + wn * (NT / 2) + ni * 8 + 2 * t;
                float b0 = bias[col], b1 = bias[col + 1];
                *(float2*)(C + (size_t)row * ldc + col) =
                    make_float2(acc[mi][ni][0] + b0, acc[mi][ni][1] + b1);
                *(float2*)(C + (size_t)(row + 8) * ldc + col) =
                    make_float2(acc[mi][ni][2] + b0, acc[mi][ni][3] + b1);
            }
    } else {
        __syncthreads();
        float* sd = sm;                       // [2][128][4]
        int*   si = (int*)(sm + 1024);
        #pragma unroll
        for (int mi = 0; mi < 2; mi++)
            #pragma unroll
            for (int h = 0; h < 2; h++) {
                int rloc = wm * 32 + mi * 16 + h * 8 + g;
                float nr = nrp[by * 128 + rloc];
                float d[4] = { 3.4e38f, 3.4e38f, 3.4e38f, 3.4e38f };
                int   ci[4] = { 0, 0, 0, 0 };
                #pragma unroll
                for (int ni = 0; ni < NI; ni++)
                    #pragma unroll
                    for (int cc = 0; cc < 2; cc++) {
                        int cg = bx * NT + wn * (NT / 2) + ni * 8 + 2 * t + cc;
                        float dd = (nr - 2.f * acc[mi][ni][h * 2 + cc]) + enp[cg];
                        ins4(d, ci, dd, cg);
                    }
                #pragma unroll
                for (int o = 1; o < 4; o <<= 1) {
                    float od[4]; int oi[4];
                    #pragma unroll
                    for (int q = 0; q < 4; q++) {
                        od[q] = __shfl_xor_sync(0xffffffffu, d[q], o);
                        oi[q] = __shfl_xor_sync(0xffffffffu, ci[q], o);
                    }
                    #pragma unroll
                    for (int q = 0; q < 4; q++) ins4(d, ci, od[q], oi[q]);
                }
                if (t == 0) {
                    int base = (wn * 128 + rloc) * 4;
                    #pragma unroll
                    for (int q = 0; q < 4; q++) { sd[base + q] = d[q]; si[base + q] = ci[q]; }
                }
            }
        __syncthreads();
        if (tid < 128) {
            float d[4]; int ci[4];
            #pragma unroll
            for (int q = 0; q < 4; q++) { d[q] = sd[tid * 4 + q]; ci[q] = si[tid * 4 + q]; }
            #pragma unroll
            for (int q = 0; q < 4; q++)
                ins4(d, ci, sd[(128 + tid) * 4 + q], si[(128 + tid) * 4 + q]);
            size_t tok = (size_t)by * 128 + tid;
            #pragma unroll
            for (int q = 0; q < 4; q++)
                candp[(size_t)(bx * 4 + q) * BN_TOK + tok] = ci[q];
        }
    }
}

// ---------------- codebook squared norms ----------------
__device__ __forceinline__ float dot256d(const float* a, const float* b) {
    const float4* a4 = (const float4*)a; const float4* b4 = (const float4*)b;
    float s = 0.f;
    #pragma unroll 8
    for (int i = 0; i < 64; i++) {
        float4 x = a4[i], y = b4[i];
        s = fmaf(x.x, y.x, s); s = fmaf(x.y, y.y, s);
        s = fmaf(x.z, y.z, s); s = fmaf(x.w, y.w, s);
    }
    return s;
}
__global__ void norm_kernel(const float* __restrict__ e0, const float* __restrict__ e1,
                            const float* __restrict__ e2) {
    int j = blockIdx.x * blockDim.x + threadIdx.x;
    if (j >= 448) return;
    const float* r;
    if (j < KC0)            r = e0 + j * PDIM;
    else if (j < KC0 + KC1) r = e1 + (j - KC0) * PDIM;
    else                    r = e2 + (j - KC0 - KC1) * PDIM;
    g_enorm[j] = dot256d(r, r);
}

// ---------------- per-token ||z_proj||^2 ----------------
__global__ void rownorm_kernel() {
    int tk = blockIdx.x * 8 + (threadIdx.x >> 5);
    int lane = threadIdx.x & 31;
    const float4* row = (const float4*)(g_zproj + (size_t)tk * PDIM);
    float s = 0.f;
    #pragma unroll
    for (int i = lane; i < 64; i += 32) {
        float4 v = row[i];
        s = fmaf(v.x, v.x, s); s = fmaf(v.y, v.y, s);
        s = fmaf(v.z, v.z, s); s = fmaf(v.w, v.w, s);
    }
    #pragma unroll
    for (int o = 16; o; o >>= 1) s += __shfl_down_sync(0xffffffffu, s, o);
    if (lane == 0) g_nr[tk] = s;
}

// ---------------- refine: exact fp32 re-rank of candidates + residual update
// MODE 0: Rout = g_R, loss init.  1: in-place.  2: qcomb = zproj - r_new.
template<int NC, int MODE>
__global__ void refine_kernel(const float* __restrict__ Rin, float* __restrict__ Rout,
                              const float* __restrict__ emb, int enoff, int level,
                              const int* __restrict__ candp, float* __restrict__ out) {
    const int warp = threadIdx.x >> 5, lane = threadIdx.x & 31;
    const int tk = blockIdx.x * 8 + warp;
    const float4* r4 = (const float4*)(Rin + (size_t)tk * PDIM);
    float4 ra = r4[lane * 2], rb = r4[lane * 2 + 1];
    float bestd = 3.4e38f; int bestc = 0x7fffffff;
    #pragma unroll
    for (int j = 0; j < NC; j++) {
        const int cj = candp[(size_t)j * BN_TOK + tk];
        const float4* e4 = (const float4*)(emb + (size_t)cj * PDIM);
        float4 ea = e4[lane * 2], eb = e4[lane * 2 + 1];
        float s = 0.f;
        s = fmaf(ra.x, ea.x, s); s = fmaf(ra.y, ea.y, s);
        s = fmaf(ra.z, ea.z, s); s = fmaf(ra.w, ea.w, s);
        s = fmaf(rb.x, eb.x, s); s = fmaf(rb.y, eb.y, s);
        s = fmaf(rb.z, eb.z, s); s = fmaf(rb.w, eb.w, s);
        #pragma unroll
        for (int o = 16; o; o >>= 1) s += __shfl_xor_sync(0xffffffffu, s, o);
        float d = __fadd_rn(g_enorm[enoff + cj], __fmul_rn(-2.f, s));
        if (d < bestd || (d == bestd && cj < bestc)) { bestd = d; bestc = cj; }
    }
    const float4* e4 = (const float4*)(emb + (size_t)bestc * PDIM);
    float4 ea = e4[lane * 2], eb = e4[lane * 2 + 1];
    float4 na, nb;
    na.x = ra.x - ea.x; na.y = ra.y - ea.y; na.z = ra.z - ea.z; na.w = ra.w - ea.w;
    nb.x = rb.x - eb.x; nb.y = rb.y - eb.y; nb.z = rb.z - eb.z; nb.w = rb.w - eb.w;
    float ns = 0.f;
    ns = fmaf(na.x, na.x, ns); ns = fmaf(na.y, na.y, ns);
    ns = fmaf(na.z, na.z, ns); ns = fmaf(na.w, na.w, ns);
    ns = fmaf(nb.x, nb.x, ns); ns = fmaf(nb.y, nb.y, ns);
    ns = fmaf(nb.z, nb.z, ns); ns = fmaf(nb.w, nb.w, ns);
    #pragma unroll
    for (int o = 16; o; o >>= 1) ns += __shfl_xor_sync(0xffffffffu, ns, o);

    if (MODE != 2) {
        float4* ro = (float4*)(Rout + (size_t)tk * PDIM);
        ro[lane * 2] = na; ro[lane * 2 + 1] = nb;
    } else {
        const float4* z4 = (const float4*)(g_zproj + (size_t)tk * PDIM);
        float4 za = z4[lane * 2], zb = z4[lane * 2 + 1];
        float4 qa, qb;
        qa.x = za.x - na.x; qa.y = za.y - na.y; qa.z = za.z - na.z; qa.w = za.w - na.w;
        qb.x = zb.x - nb.x; qb.y = zb.y - nb.y; qb.z = zb.z - nb.z; qb.w = zb.w - nb.w;
        float4* qo = (float4*)(g_qcomb + (size_t)tk * PDIM);
        qo[lane * 2] = qa; qo[lane * 2 + 1] = qb;
    }
    if (lane == 0) {
        g_nr[tk] = ns;
        if (MODE == 0) g_dmin[tk] = ns; else g_dmin[tk] += ns;
        out[OUT_IDX + level * BN_TOK + tk] = (float)bestc;
    }
}

// ---------------- loss finalize ----------------
__global__ void loss_final(float* __restrict__ out) {
    __shared__ float red[256];
    const int p = threadIdx.x;
    float s = 0.f;
    for (int i = p; i < BN_TOK; i += 256) s += g_dmin[i];
    red[p] = s;
    __syncthreads();
    for (int st = 128; st; st >>= 1) {
        if (p < st) red[p] += red[p + st];
        __syncthreads();
    }
    if (p == 0)
        out[OUT_LOSS] = 0.25f * red[0] / ((float)BN_TOK * (float)PDIM * 3.f);
}

// ---------------- launcher ----------------
extern "C" void kernel_launch(void* const* d_in, const int* in_sizes, int n_in,
                              void* d_out, int out_size) {
    const float* z     = (const float*)d_in[0];
    const float* W_in  = (const float*)d_in[1];
    const float* b_in  = (const float*)d_in[2];
    const float* W_out = (const float*)d_in[3];
    const float* b_out = (const float*)d_in[4];
    const float* e0    = (const float*)d_in[5];
    const float* e1    = (const float*)d_in[6];
    const float* e2    = (const float*)d_in[7];
    float* out = (float*)d_out;

    float *zproj, *R, *qcomb, *nr, *enorm;
    float *bwin, *bwout, *be0, *be1, *be2;
    int *cand;
    cudaGetSymbolAddress((void**)&zproj, g_zproj);
    cudaGetSymbolAddress((void**)&R,     g_R);
    cudaGetSymbolAddress((void**)&qcomb, g_qcomb);
    cudaGetSymbolAddress((void**)&nr,    g_nr);
    cudaGetSymbolAddress((void**)&enorm, g_enorm);
    cudaGetSymbolAddress((void**)&cand,  g_cand);
    cudaGetSymbolAddress((void**)&bwin,  g_BWin);
    cudaGetSymbolAddress((void**)&bwout, g_BWout);
    cudaGetSymbolAddress((void**)&be0,   g_Be0);
    cudaGetSymbolAddress((void**)&be1,   g_Be1);
    cudaGetSymbolAddress((void**)&be2,   g_Be2);

    const int SM128 = (2 * 4096 + 3 * 128 * 32) * 4;   // 32KB A + 48KB B = 81920
    const int SM64  = (2 * 4096 + 3 * 64 * 32) * 4;    // 32KB A + 24KB B = 57344
    cudaFuncSetAttribute(mma_gemm<128, 0>, cudaFuncAttributeMaxDynamicSharedMemorySize, SM128);
    cudaFuncSetAttribute(mma_gemm<128, 1>, cudaFuncAttributeMaxDynamicSharedMemorySize, SM128);
    cudaFuncSetAttribute(mma_gemm<64, 1>,  cudaFuncAttributeMaxDynamicSharedMemorySize, SM64);

    // operand prep (B images) + codebook norms
    bprep<128><<<(256 * 1408 + 255) / 256, 256>>>(W_in,  bwin,  1408, 256,  1, 256 * 1408);
    bprep<128><<<(1408 * 256 + 255) / 256, 256>>>(W_out, bwout, 256,  1408, 1, 1408 * 256);
    bprep<64> <<<(64 * 256 + 255) / 256,   256>>>(e0,    be0,   256,  256,  0, 64 * 256);
    bprep<128><<<(128 * 256 + 255) / 256,  256>>>(e1,    be1,   256,  256,  0, 128 * 256);
    bprep<128><<<(256 * 256 + 255) / 256,  256>>>(e2,    be2,   256,  256,  0, 256 * 256);
    norm_kernel<<<2, 256>>>(e0, e1, e2);

    // z_proj = z @ W_in + b_in     [32768,1408] x [1408,256]
    mma_gemm<128, 0><<<dim3(2, BN_TOK / 128), 256, SM128>>>(
        DDIM, DDIM, PDIM, z, bwin, b_in, zproj, nullptr, nullptr, nullptr);
    rownorm_kernel<<<BN_TOK / 8, 256>>>();

    // level 0 (64 codes) -> 4 candidates
    mma_gemm<64, 1><<<dim3(1, BN_TOK / 128), 256, SM64>>>(
        PDIM, PDIM, 0, zproj, be0, nullptr, nullptr, nr, enorm, cand);
    refine_kernel<4, 0><<<BN_TOK / 8, 256>>>(zproj, R, e0, 0, 0, cand, out);

    // level 1 (128 codes) -> 4 candidates
    mma_gemm<128, 1><<<dim3(1, BN_TOK / 128), 256, SM128>>>(
        PDIM, PDIM, 0, R, be1, nullptr, nullptr, nr, enorm + KC0, cand);
    refine_kernel<4, 1><<<BN_TOK / 8, 256>>>(R, R, e1, KC0, 1, cand, out);

    // level 2 (256 codes; two N-blocks) -> 8 candidates
    mma_gemm<128, 1><<<dim3(2, BN_TOK / 128), 256, SM128>>>(
        PDIM, PDIM, 0, R, be2, nullptr, nullptr, nr, enorm + KC0 + KC1, cand);
    refine_kernel<8, 2><<<BN_TOK / 8, 256>>>(R, nullptr, e2, KC0 + KC1, 2, cand, out);

    loss_final<<<1, 256>>>(out);

    // z_q_out = qcomb @ W_out + b_out   [32768,256] x [256,1408]
    mma_gemm<128, 0><<<dim3(11, BN_TOK / 128), 256, SM128>>>(
        PDIM, PDIM, DDIM, qcomb, bwout, b_out, out, nullptr, nullptr, nullptr);
}